// round 4
// baseline (speedup 1.0000x reference)
#include <cuda_runtime.h>
#include <cuda_fp16.h>
#include <cstdint>

#define TOK  8192
#define INF  4096
#define OUTF 4096
#define RANK 64

// ---------------- static device scratch (allocation-free rule) ----------------
__device__ __half g_X16[TOK * INF];    // 64 MB
__device__ __half g_W16[OUTF * INF];   // 32 MB
__device__ __half g_A16[RANK * INF];   // 512 KB
__device__ __half g_B16[OUTF * RANK];  // 512 KB
__device__ __half g_T16[TOK * RANK];   // 1 MB

__constant__ float c_nf4[16] = {
    -1.0f, -0.6961928009986877f, -0.5250730514526367f, -0.39491748809814453f,
    -0.28444138169288635f, -0.18477343022823334f, -0.09105003625154495f, 0.0f,
    0.07958029955625534f, 0.16093020141124725f, 0.2461123913526535f,
    0.33791524171829224f, 0.44070982933044434f, 0.5626170039176941f,
    0.7229568362236023f, 1.0f};

// ---------------- PTX helpers (plain-sm_100-safe: sm_75/80 features only) ----
__device__ __forceinline__ uint32_t s2u(const void* p) {
    uint32_t a;
    asm("{ .reg .u64 t; cvta.to.shared.u64 t, %1; cvt.u32.u64 %0, t; }"
        : "=r"(a) : "l"(p));
    return a;
}

#define CPA16(smem, gmem) \
    asm volatile("cp.async.cg.shared.global [%0], [%1], 16;" :: "r"(smem), "l"(gmem) : "memory")
#define CPA_COMMIT() asm volatile("cp.async.commit_group;" ::: "memory")
#define CPA_WAIT2()  asm volatile("cp.async.wait_group 2;" ::: "memory")

__device__ __forceinline__ void ldsm4(uint32_t* r, uint32_t addr) {
    asm volatile("ldmatrix.sync.aligned.m8n8.x4.shared.b16 {%0,%1,%2,%3}, [%4];"
                 : "=r"(r[0]), "=r"(r[1]), "=r"(r[2]), "=r"(r[3]) : "r"(addr));
}

#define MMA16816(d, a, b)                                                      \
    asm volatile(                                                              \
        "mma.sync.aligned.m16n8k16.row.col.f32.f16.f16.f32 "                   \
        "{%0,%1,%2,%3}, {%4,%5,%6,%7}, {%8,%9}, {%0,%1,%2,%3};"                \
        : "+f"((d)[0]), "+f"((d)[1]), "+f"((d)[2]), "+f"((d)[3])               \
        : "r"((a)[0]), "r"((a)[1]), "r"((a)[2]), "r"((a)[3]),                  \
          "r"((b)[0]), "r"((b)[1]))

// ---------------- pre-pass kernels (write __device__ scratch directly) -------
__global__ void k_convert_x(const float* __restrict__ in) {
    int i = blockIdx.x * blockDim.x + threadIdx.x;   // one 8-elem group
    const float4* p = (const float4*)in;
    float4 a = p[2 * i], b = p[2 * i + 1];
    __half2 h0 = __floats2half2_rn(a.x, a.y), h1 = __floats2half2_rn(a.z, a.w);
    __half2 h2 = __floats2half2_rn(b.x, b.y), h3 = __floats2half2_rn(b.z, b.w);
    uint4 o;
    o.x = *(uint32_t*)&h0; o.y = *(uint32_t*)&h1;
    o.z = *(uint32_t*)&h2; o.w = *(uint32_t*)&h3;
    ((uint4*)g_X16)[i] = o;
}

__global__ void k_convert_lora(const float* __restrict__ A, const float* __restrict__ B) {
    int i = blockIdx.x * blockDim.x + threadIdx.x;   // 65536 float4 per array
    float4 a = ((const float4*)A)[i];
    float4 b = ((const float4*)B)[i];
    __half2 a0 = __floats2half2_rn(a.x, a.y), a1 = __floats2half2_rn(a.z, a.w);
    __half2 b0 = __floats2half2_rn(b.x, b.y), b1 = __floats2half2_rn(b.z, b.w);
    uint2 oa, ob;
    oa.x = *(uint32_t*)&a0; oa.y = *(uint32_t*)&a1;
    ob.x = *(uint32_t*)&b0; ob.y = *(uint32_t*)&b1;
    ((uint2*)g_A16)[i] = oa;
    ((uint2*)g_B16)[i] = ob;
}

__global__ void k_dequant(const int* __restrict__ q, const float* __restrict__ am) {
    int i = blockIdx.x * blockDim.x + threadIdx.x;
    int4 q0 = ((const int4*)q)[2 * i];
    int4 q1 = ((const int4*)q)[2 * i + 1];
    float s = am[i >> 3];  // 8 elems/thread, all inside one 64-block
    __half2 h0 = __floats2half2_rn(c_nf4[q0.x] * s, c_nf4[q0.y] * s);
    __half2 h1 = __floats2half2_rn(c_nf4[q0.z] * s, c_nf4[q0.w] * s);
    __half2 h2 = __floats2half2_rn(c_nf4[q1.x] * s, c_nf4[q1.y] * s);
    __half2 h3 = __floats2half2_rn(c_nf4[q1.z] * s, c_nf4[q1.w] * s);
    uint4 o;
    o.x = *(uint32_t*)&h0; o.y = *(uint32_t*)&h1;
    o.z = *(uint32_t*)&h2; o.w = *(uint32_t*)&h3;
    ((uint4*)g_W16)[i] = o;
}

// ---------------- mma.sync fp16 GEMM: C[M-tile, N-tile] = A @ B^T ------------
// Operands come from __device__ scratch (selected by template flags, no host
// pointer plumbing): MAIN ? (A=g_X16 [TOK,INF], B=g_W16 [OUTF,INF], tail
// chunks from g_T16/g_B16, fp32 out + bias) : (A=g_X16, B=g_A16 [RANK,INF],
// fp16 out g_T16 [TOK,RANK]).
// BM=128, K chunk 32, 4-stage cp.async pipeline, 8 warps (4x2), warp 32x(BN/2).
// Smem rows PITCH=80B (64B data + 16B pad): row offset 80r mod 128 covers all
// eight 16B groups => ldmatrix conflict-free without XOR swizzle.
template <bool MAIN>
__global__ void __launch_bounds__(256) mma_gemm(
    float* __restrict__ outF, const float* __restrict__ bias) {
    constexpr int BM = 128;
    constexpr int BN = MAIN ? 128 : 64;
    constexpr int PITCH = 80;               // bytes per smem row
    constexpr int A_BY = BM * PITCH;        // 10240
    constexpr int B_BY = BN * PITCH;
    constexpr int STG = A_BY + B_BY;        // per-stage bytes
    constexpr int STAGES = 4;
    constexpr int NT = BN / 16;             // n8 tiles per warp (warp N = BN/2)
    constexpr int NBJ = (BN * 4) / 256;     // B cp.async chunks per thread
    constexpr int KMAIN = INF / 32;
    constexpr int KTOT = MAIN ? (KMAIN + RANK / 32) : KMAIN;

    extern __shared__ char dsm[];
    __shared__ float s_bias[128];

    const __half* __restrict__ Ap = g_X16;
    const __half* __restrict__ Bp = MAIN ? g_W16 : g_A16;
    const __half* __restrict__ A2 = g_T16;
    const __half* __restrict__ B2 = g_B16;

    const int tid = threadIdx.x;
    const int lane = tid & 31, wid = tid >> 5;
    const int wm = (wid & 3) * 32;          // warp M offset in tile
    const int wn = (wid >> 2) * (BN / 2);   // warp N offset in tile

    int mt, nt;
    if (MAIN) {
        constexpr int GROUP = 16;
        constexpr int NTN = OUTF / BN;      // 32
        int gsz = GROUP * NTN;
        int g = blockIdx.x / gsz, r = blockIdx.x % gsz;
        mt = g * GROUP + (r % GROUP);
        nt = r / GROUP;
    } else {
        mt = blockIdx.x; nt = 0;
    }
    const int m0 = mt * BM, n0 = nt * BN;

    const uint32_t sb = s2u(dsm);

    if (MAIN) {
        for (int i = tid; i < BN; i += 256) s_bias[i] = bias[n0 + i];
    }

    // ---- cp.async slots: A has 512 16B-chunks/stage, B has BN*4 ----
    uint32_t soA[2]; const __half* gA[2]; const __half* tA[2];
#pragma unroll
    for (int j = 0; j < 2; j++) {
        int id = tid + 256 * j;             // 0..511
        int row = id >> 2, g = id & 3;
        soA[j] = row * PITCH + g * 16;
        gA[j] = Ap + (size_t)(m0 + row) * INF + g * 8;
        tA[j] = A2 + (size_t)(m0 + row) * RANK + g * 8;
    }
    uint32_t soB[NBJ]; const __half* gB[NBJ]; const __half* tB[NBJ];
#pragma unroll
    for (int j = 0; j < NBJ; j++) {
        int id = tid + 256 * j;
        int row = id >> 2, g = id & 3;
        soB[j] = A_BY + row * PITCH + g * 16;
        gB[j] = Bp + (size_t)(n0 + row) * INF + g * 8;
        tB[j] = B2 + (size_t)(n0 + row) * RANK + g * 8;
    }

    auto load_chunk = [&](int k, int s) {
        uint32_t so = (uint32_t)s * STG + sb;
        if (!MAIN || k < KMAIN) {
#pragma unroll
            for (int j = 0; j < 2; j++)   CPA16(so + soA[j], gA[j] + (size_t)k * 32);
#pragma unroll
            for (int j = 0; j < NBJ; j++) CPA16(so + soB[j], gB[j] + (size_t)k * 32);
        } else {
            int kt = k - KMAIN;
#pragma unroll
            for (int j = 0; j < 2; j++)   CPA16(so + soA[j], tA[j] + (size_t)kt * 32);
#pragma unroll
            for (int j = 0; j < NBJ; j++) CPA16(so + soB[j], tB[j] + (size_t)kt * 32);
        }
    };

    // ---- ldmatrix per-thread offsets ----
    uint32_t aoff[2], boff[NT / 2];
#pragma unroll
    for (int q = 0; q < 2; q++)
        aoff[q] = (wm + q * 16 + (lane & 15)) * PITCH + (lane >> 4) * 16;
#pragma unroll
    for (int q = 0; q < NT / 2; q++)
        boff[q] = A_BY + (wn + q * 16 + (lane & 15)) * PITCH + (lane >> 4) * 16;

    float acc[2][NT][4];
#pragma unroll
    for (int a = 0; a < 2; a++)
#pragma unroll
        for (int b = 0; b < NT; b++)
#pragma unroll
            for (int c = 0; c < 4; c++) acc[a][b][c] = 0.f;

    // ---- prologue: fill 3 of 4 stages ----
#pragma unroll
    for (int k = 0; k < STAGES - 1; k++) {
        load_chunk(k, k);
        CPA_COMMIT();
    }

    // ---- main loop ----
    for (int k = 0; k < KTOT; k++) {
        CPA_WAIT2();       // chunk k resident (<=2 newer groups pending)
        __syncthreads();   // all warps done with the stage being overwritten
        if (k + STAGES - 1 < KTOT) load_chunk(k + STAGES - 1, (k + STAGES - 1) & 3);
        CPA_COMMIT();      // unconditional: uniform group accounting

        uint32_t stg = sb + (uint32_t)(k & 3) * STG;
#pragma unroll
        for (int kk = 0; kk < 2; kk++) {
            uint32_t af[2][4];
#pragma unroll
            for (int q = 0; q < 2; q++) ldsm4(af[q], stg + aoff[q] + kk * 32);
            uint32_t bf[NT][2];
#pragma unroll
            for (int q = 0; q < NT / 2; q++) {
                uint32_t r[4];
                ldsm4(r, stg + boff[q] + kk * 32);
                bf[2 * q][0] = r[0]; bf[2 * q][1] = r[2];
                bf[2 * q + 1][0] = r[1]; bf[2 * q + 1][1] = r[3];
            }
#pragma unroll
            for (int a = 0; a < 2; a++)
#pragma unroll
                for (int b = 0; b < NT; b++) MMA16816(acc[a][b], af[a], bf[b]);
        }
    }

    // ---- epilogue ----
    const int gr = lane >> 2, c2 = (lane & 3) * 2;
#pragma unroll
    for (int a = 0; a < 2; a++) {
#pragma unroll
        for (int b = 0; b < NT; b++) {
            int row = m0 + wm + a * 16 + gr;
            int coll = wn + b * 8 + c2;
            if (MAIN) {
                int col = n0 + coll;
                float2 v0 = {acc[a][b][0] + s_bias[coll],
                             acc[a][b][1] + s_bias[coll + 1]};
                float2 v1 = {acc[a][b][2] + s_bias[coll],
                             acc[a][b][3] + s_bias[coll + 1]};
                *(float2*)(outF + (size_t)row * OUTF + col) = v0;
                *(float2*)(outF + (size_t)(row + 8) * OUTF + col) = v1;
            } else {
                __half2 h0 = __floats2half2_rn(acc[a][b][0], acc[a][b][1]);
                __half2 h1 = __floats2half2_rn(acc[a][b][2], acc[a][b][3]);
                *(__half2*)(g_T16 + (size_t)row * RANK + coll) = h0;
                *(__half2*)(g_T16 + (size_t)(row + 8) * RANK + coll) = h1;
            }
        }
    }
}

// ---------------- launch ----------------
extern "C" void kernel_launch(void* const* d_in, const int* in_sizes, int n_in,
                              void* d_out, int out_size) {
    const float* x    = (const float*)d_in[0];
    const int*   qc   = (const int*)d_in[1];
    const float* am   = (const float*)d_in[2];
    const float* lA   = (const float*)d_in[3];
    const float* lB   = (const float*)d_in[4];
    const float* bias = (const float*)d_in[5];
    float* out = (float*)d_out;

    constexpr int SM_T = 4 * (128 + 64) * 80;    // 61,440
    constexpr int SM_M = 4 * (128 + 128) * 80;   // 81,920
    cudaFuncSetAttribute(mma_gemm<false>,
                         cudaFuncAttributeMaxDynamicSharedMemorySize, SM_T);
    cudaFuncSetAttribute(mma_gemm<true>,
                         cudaFuncAttributeMaxDynamicSharedMemorySize, SM_M);

    // 1) x -> fp16 (g_X16)
    k_convert_x<<<TOK * INF / 8 / 256, 256>>>(x);
    // 2) lora_A / lora_B -> fp16 (g_A16, g_B16)
    k_convert_lora<<<(RANK * INF / 4) / 256, 256>>>(lA, lB);
    // 3) NF4 dequant -> fp16 (g_W16)
    k_dequant<<<OUTF * INF / 8 / 256, 256>>>(qc, am);
    // 4) T = X @ A^T  -> g_T16 [8192, 64] fp16
    mma_gemm<false><<<TOK / 128, 256, SM_T>>>(nullptr, nullptr);
    // 5) out = X @ W^T + T @ B^T + bias  (LoRA fused as 2 tail K-chunks)
    mma_gemm<true><<<(TOK / 128) * (OUTF / 128), 256, SM_M>>>(out, bias);
}

// round 5
// speedup vs baseline: 1.0245x; 1.0245x over previous
#include <cuda_runtime.h>
#include <cuda_fp16.h>
#include <cstdint>

#define TOK  8192
#define INF  4096
#define OUTF 4096
#define RANK 64

// ---------------- static device scratch (allocation-free rule) ----------------
__device__ __half g_X16[TOK * INF];    // 64 MB
__device__ __half g_W16[OUTF * INF];   // 32 MB
__device__ __half g_A16[RANK * INF];   // 512 KB
__device__ __half g_B16[OUTF * RANK];  // 512 KB
__device__ __half g_T16[TOK * RANK];   // 1 MB

__constant__ float c_nf4[16] = {
    -1.0f, -0.6961928009986877f, -0.5250730514526367f, -0.39491748809814453f,
    -0.28444138169288635f, -0.18477343022823334f, -0.09105003625154495f, 0.0f,
    0.07958029955625534f, 0.16093020141124725f, 0.2461123913526535f,
    0.33791524171829224f, 0.44070982933044434f, 0.5626170039176941f,
    0.7229568362236023f, 1.0f};

// ---------------- PTX helpers (plain-sm_100-safe) ----------------------------
__device__ __forceinline__ uint32_t s2u(const void* p) {
    uint32_t a;
    asm("{ .reg .u64 t; cvta.to.shared.u64 t, %1; cvt.u32.u64 %0, t; }"
        : "=r"(a) : "l"(p));
    return a;
}

#define CPA16(smem, gmem) \
    asm volatile("cp.async.cg.shared.global [%0], [%1], 16;" :: "r"(smem), "l"(gmem) : "memory")
#define CPA_COMMIT() asm volatile("cp.async.commit_group;" ::: "memory")
#define CPA_WAIT1()  asm volatile("cp.async.wait_group 1;" ::: "memory")

__device__ __forceinline__ void ldsm4(uint32_t* r, uint32_t addr) {
    asm volatile("ldmatrix.sync.aligned.m8n8.x4.shared.b16 {%0,%1,%2,%3}, [%4];"
                 : "=r"(r[0]), "=r"(r[1]), "=r"(r[2]), "=r"(r[3]) : "r"(addr));
}

#define MMA16816(d, a, b)                                                      \
    asm volatile(                                                              \
        "mma.sync.aligned.m16n8k16.row.col.f32.f16.f16.f32 "                   \
        "{%0,%1,%2,%3}, {%4,%5,%6,%7}, {%8,%9}, {%0,%1,%2,%3};"                \
        : "+f"((d)[0]), "+f"((d)[1]), "+f"((d)[2]), "+f"((d)[3])               \
        : "r"((a)[0]), "r"((a)[1]), "r"((a)[2]), "r"((a)[3]),                  \
          "r"((b)[0]), "r"((b)[1]))

// ---------------- pre-pass kernels ----------------
__global__ void k_convert_x(const float* __restrict__ in) {
    int i = blockIdx.x * blockDim.x + threadIdx.x;
    const float4* p = (const float4*)in;
    float4 a = p[2 * i], b = p[2 * i + 1];
    __half2 h0 = __floats2half2_rn(a.x, a.y), h1 = __floats2half2_rn(a.z, a.w);
    __half2 h2 = __floats2half2_rn(b.x, b.y), h3 = __floats2half2_rn(b.z, b.w);
    uint4 o;
    o.x = *(uint32_t*)&h0; o.y = *(uint32_t*)&h1;
    o.z = *(uint32_t*)&h2; o.w = *(uint32_t*)&h3;
    ((uint4*)g_X16)[i] = o;
}

__global__ void k_convert_lora(const float* __restrict__ A, const float* __restrict__ B) {
    int i = blockIdx.x * blockDim.x + threadIdx.x;
    float4 a = ((const float4*)A)[i];
    float4 b = ((const float4*)B)[i];
    __half2 a0 = __floats2half2_rn(a.x, a.y), a1 = __floats2half2_rn(a.z, a.w);
    __half2 b0 = __floats2half2_rn(b.x, b.y), b1 = __floats2half2_rn(b.z, b.w);
    uint2 oa, ob;
    oa.x = *(uint32_t*)&a0; oa.y = *(uint32_t*)&a1;
    ob.x = *(uint32_t*)&b0; ob.y = *(uint32_t*)&b1;
    ((uint2*)g_A16)[i] = oa;
    ((uint2*)g_B16)[i] = ob;
}

__global__ void k_dequant(const int* __restrict__ q, const float* __restrict__ am) {
    int i = blockIdx.x * blockDim.x + threadIdx.x;
    int4 q0 = ((const int4*)q)[2 * i];
    int4 q1 = ((const int4*)q)[2 * i + 1];
    float s = am[i >> 3];
    __half2 h0 = __floats2half2_rn(c_nf4[q0.x] * s, c_nf4[q0.y] * s);
    __half2 h1 = __floats2half2_rn(c_nf4[q0.z] * s, c_nf4[q0.w] * s);
    __half2 h2 = __floats2half2_rn(c_nf4[q1.x] * s, c_nf4[q1.y] * s);
    __half2 h3 = __floats2half2_rn(c_nf4[q1.z] * s, c_nf4[q1.w] * s);
    uint4 o;
    o.x = *(uint32_t*)&h0; o.y = *(uint32_t*)&h1;
    o.z = *(uint32_t*)&h2; o.w = *(uint32_t*)&h3;
    ((uint4*)g_W16)[i] = o;
}

// ---------------- mma.sync fp16 GEMM: C[M-tile, N-tile] = A @ B^T ------------
// BM x BN CTA tile, 8 warps as BMW x (8/BMW), warp tile 32 x (BN/(8/BMW)).
// 3-stage cp.async pipeline, K chunk 32. PITCH=80B rows: 80r mod 128 covers
// all eight 16B bank groups => ldmatrix conflict-free without swizzle.
// MAIN: A=g_X16, B=g_W16, +2 tail K-chunks (g_T16/g_B16) = fused LoRA,
//       fp32 out + bias. Else: A=g_X16, B=g_A16, fp16 out -> g_T16.
template <int BM, int BN, int BMW, bool MAIN>
__global__ void __launch_bounds__(256, 2) mma_gemm(
    float* __restrict__ outF, const float* __restrict__ bias) {
    constexpr int PITCH = 80;
    constexpr int A_BY = BM * PITCH;
    constexpr int STG = (BM + BN) * PITCH;
    constexpr int STAGES = 3;
    constexpr int WN = BN / (8 / BMW);      // warp N extent
    constexpr int NT = WN / 8;              // n8 tiles per warp
    constexpr int NAJ = BM * 4 / 256;       // A cp.async chunks per thread
    constexpr int NBJ = BN * 4 / 256;       // B cp.async chunks per thread
    constexpr int KMAIN = INF / 32;
    constexpr int KTOT = MAIN ? (KMAIN + RANK / 32) : KMAIN;

    extern __shared__ char dsm[];
    __shared__ float s_bias[BN];

    const __half* __restrict__ Ap = g_X16;
    const __half* __restrict__ Bp = MAIN ? g_W16 : g_A16;

    const int tid = threadIdx.x;
    const int lane = tid & 31, wid = tid >> 5;
    const int wm = (wid % BMW) * 32;
    const int wn = (wid / BMW) * WN;

    int mt, nt;
    if (MAIN) {
        constexpr int GROUP = 16;
        constexpr int NTN = OUTF / BN;
        int gsz = GROUP * NTN;
        int g = blockIdx.x / gsz, r = blockIdx.x % gsz;
        mt = g * GROUP + (r % GROUP);
        nt = r / GROUP;
    } else {
        mt = blockIdx.x; nt = 0;
    }
    const int m0 = mt * BM, n0 = nt * BN;

    const uint32_t sb = s2u(dsm);

    if (MAIN) {
        for (int i = tid; i < BN; i += 256) s_bias[i] = bias[n0 + i];
    }

    // ---- cp.async slots ----
    uint32_t soA[NAJ]; const __half* gA[NAJ]; int rowA[NAJ], colA[NAJ];
#pragma unroll
    for (int j = 0; j < NAJ; j++) {
        int id = tid + 256 * j;
        int row = id >> 2, g = id & 3;
        soA[j] = row * PITCH + g * 16;
        gA[j] = Ap + (size_t)(m0 + row) * INF + g * 8;
        rowA[j] = row; colA[j] = g * 8;
    }
    uint32_t soB[NBJ]; const __half* gB[NBJ]; int rowB[NBJ], colB[NBJ];
#pragma unroll
    for (int j = 0; j < NBJ; j++) {
        int id = tid + 256 * j;
        int row = id >> 2, g = id & 3;
        soB[j] = A_BY + row * PITCH + g * 16;
        gB[j] = Bp + (size_t)(n0 + row) * INF + g * 8;
        rowB[j] = row; colB[j] = g * 8;
    }

    auto load_chunk = [&](int k, int s) {
        uint32_t so = (uint32_t)s * STG + sb;
        if (!MAIN || k < KMAIN) {
#pragma unroll
            for (int j = 0; j < NAJ; j++) CPA16(so + soA[j], gA[j] + (size_t)k * 32);
#pragma unroll
            for (int j = 0; j < NBJ; j++) CPA16(so + soB[j], gB[j] + (size_t)k * 32);
        } else {
            // LoRA tail: pointers computed lazily (runs twice) to save regs
            int kt = k - KMAIN;
#pragma unroll
            for (int j = 0; j < NAJ; j++)
                CPA16(so + soA[j],
                      g_T16 + (size_t)(m0 + rowA[j]) * RANK + kt * 32 + colA[j]);
#pragma unroll
            for (int j = 0; j < NBJ; j++)
                CPA16(so + soB[j],
                      g_B16 + (size_t)(n0 + rowB[j]) * RANK + kt * 32 + colB[j]);
        }
    };

    // ---- ldmatrix per-thread offsets ----
    uint32_t aoff[2], boff[NT / 2];
#pragma unroll
    for (int q = 0; q < 2; q++)
        aoff[q] = (wm + q * 16 + (lane & 15)) * PITCH + (lane >> 4) * 16;
#pragma unroll
    for (int q = 0; q < NT / 2; q++)
        boff[q] = A_BY + (wn + q * 16 + (lane & 15)) * PITCH + (lane >> 4) * 16;

    float acc[2][NT][4];
#pragma unroll
    for (int a = 0; a < 2; a++)
#pragma unroll
        for (int b = 0; b < NT; b++)
#pragma unroll
            for (int c = 0; c < 4; c++) acc[a][b][c] = 0.f;

    // ---- prologue: fill 2 of 3 stages ----
#pragma unroll
    for (int k = 0; k < STAGES - 1; k++) {
        load_chunk(k, k);
        CPA_COMMIT();
    }

    // ---- main loop ----
    int s = 0;                 // stage of chunk k
    for (int k = 0; k < KTOT; k++) {
        CPA_WAIT1();           // chunk k resident (chunk k+1 may be in flight)
        __syncthreads();       // all warps done with the stage being overwritten
        if (k + STAGES - 1 < KTOT) {
            int s2 = s + 2; if (s2 >= STAGES) s2 -= STAGES;
            load_chunk(k + STAGES - 1, s2);
        }
        CPA_COMMIT();          // unconditional: uniform group accounting

        uint32_t stg = sb + (uint32_t)s * STG;
#pragma unroll
        for (int kk = 0; kk < 2; kk++) {
            uint32_t af[2][4];
#pragma unroll
            for (int q = 0; q < 2; q++) ldsm4(af[q], stg + aoff[q] + kk * 32);
            uint32_t bf[NT][2];
#pragma unroll
            for (int q = 0; q < NT / 2; q++) {
                uint32_t r[4];
                ldsm4(r, stg + boff[q] + kk * 32);
                bf[2 * q][0] = r[0]; bf[2 * q][1] = r[2];
                bf[2 * q + 1][0] = r[1]; bf[2 * q + 1][1] = r[3];
            }
#pragma unroll
            for (int a = 0; a < 2; a++)
#pragma unroll
                for (int b = 0; b < NT; b++) MMA16816(acc[a][b], af[a], bf[b]);
        }
        s++; if (s == STAGES) s = 0;
    }

    // ---- epilogue ----
    const int gr = lane >> 2, c2 = (lane & 3) * 2;
#pragma unroll
    for (int a = 0; a < 2; a++) {
#pragma unroll
        for (int b = 0; b < NT; b++) {
            int row = m0 + wm + a * 16 + gr;
            int coll = wn + b * 8 + c2;
            if (MAIN) {
                int col = n0 + coll;
                float2 v0 = {acc[a][b][0] + s_bias[coll],
                             acc[a][b][1] + s_bias[coll + 1]};
                float2 v1 = {acc[a][b][2] + s_bias[coll],
                             acc[a][b][3] + s_bias[coll + 1]};
                *(float2*)(outF + (size_t)row * OUTF + col) = v0;
                *(float2*)(outF + (size_t)(row + 8) * OUTF + col) = v1;
            } else {
                __half2 h0 = __floats2half2_rn(acc[a][b][0], acc[a][b][1]);
                __half2 h1 = __floats2half2_rn(acc[a][b][2], acc[a][b][3]);
                *(__half2*)(g_T16 + (size_t)row * RANK + coll) = h0;
                *(__half2*)(g_T16 + (size_t)(row + 8) * RANK + coll) = h1;
            }
        }
    }
}

// ---------------- launch ----------------
extern "C" void kernel_launch(void* const* d_in, const int* in_sizes, int n_in,
                              void* d_out, int out_size) {
    const float* x    = (const float*)d_in[0];
    const int*   qc   = (const int*)d_in[1];
    const float* am   = (const float*)d_in[2];
    const float* lA   = (const float*)d_in[3];
    const float* lB   = (const float*)d_in[4];
    const float* bias = (const float*)d_in[5];
    float* out = (float*)d_out;

    constexpr int SM_T = 3 * (64 + 64) * 80;     // 30,720
    constexpr int SM_M = 3 * (128 + 128) * 80;   // 61,440 -> 2 CTAs/SM
    cudaFuncSetAttribute((const void*)mma_gemm<64, 64, 2, false>,
                         cudaFuncAttributeMaxDynamicSharedMemorySize, SM_T);
    cudaFuncSetAttribute((const void*)mma_gemm<128, 128, 4, true>,
                         cudaFuncAttributeMaxDynamicSharedMemorySize, SM_M);

    // 1) x -> fp16 (g_X16)
    k_convert_x<<<TOK * INF / 8 / 256, 256>>>(x);
    // 2) lora_A / lora_B -> fp16 (g_A16, g_B16)
    k_convert_lora<<<(RANK * INF / 4) / 256, 256>>>(lA, lB);
    // 3) NF4 dequant -> fp16 (g_W16)
    k_dequant<<<OUTF * INF / 8 / 256, 256>>>(qc, am);
    // 4) T = X @ A^T -> g_T16 [8192, 64] fp16   (BM=64: 128 CTAs, full wave)
    mma_gemm<64, 64, 2, false><<<TOK / 64, 256, SM_T>>>(nullptr, nullptr);
    // 5) out = X @ W^T + T @ B^T + bias  (LoRA fused as 2 tail K-chunks)
    mma_gemm<128, 128, 4, true><<<(TOK / 128) * (OUTF / 128), 256, SM_M>>>(out, bias);
}